// round 17
// baseline (speedup 1.0000x reference)
#include <cuda_runtime.h>
#include <cuda_bf16.h>
#include <math.h>
#include <stdint.h>

#define NUM_H 24
#define LQ 1280
#define LK 2304

// ---------------- scratch (device globals; no allocations) ----------------
__device__ float g_q[4*24*1280*64];      // (B,H,LQ,64)
__device__ float g_k[4*24*2304*64];
__device__ float g_v[4*24*2304*64];
__device__ float g_mq[6144], g_sq[6144], g_mk[6144], g_sk[6144];
__device__ float g_ps[2*96*4*64], g_pss[2*96*4*64];
__device__ uint4 g_kf[96*36*1024];
__device__ uint4 g_vf[96*36*1024];
__device__ uint32_t g_hsh[4096*768], g_hsl[4096*768];
__device__ uint32_t g_esh[1024*768], g_esl[1024*768];
__device__ uint32_t g_aoh[4096*768], g_aol[4096*768];
__device__ uint32_t g_eoh[1024*768], g_eol[1024*768];
__device__ uint4 g_wp[8*12*48*1024];

// ---------------- bf16 helpers ----------------
__device__ __forceinline__ void split_pair(float x, float y, uint32_t &hi, uint32_t &lo){
    __nv_bfloat162 hv = __floats2bfloat162_rn(x, y);
    hi = *reinterpret_cast<uint32_t*>(&hv);
    float rx = x - __low2float(hv);
    float ry = y - __high2float(hv);
    __nv_bfloat162 lv = __floats2bfloat162_rn(rx, ry);
    lo = *reinterpret_cast<uint32_t*>(&lv);
}

__device__ __forceinline__ void mma16(float* c, const uint32_t* a, uint32_t b0, uint32_t b1){
    asm volatile("mma.sync.aligned.m16n8k16.row.col.f32.bf16.bf16.f32 "
        "{%0,%1,%2,%3},{%4,%5,%6,%7},{%8,%9},{%0,%1,%2,%3};"
        : "+f"(c[0]),"+f"(c[1]),"+f"(c[2]),"+f"(c[3])
        : "r"(a[0]),"r"(a[1]),"r"(a[2]),"r"(a[3]),"r"(b0),"r"(b1));
}

__device__ __forceinline__ void ldsm4(uint32_t* r, uint32_t addr){
    asm volatile("ldmatrix.sync.aligned.m8n8.x4.shared.b16 {%0,%1,%2,%3}, [%4];"
        : "=r"(r[0]),"=r"(r[1]),"=r"(r[2]),"=r"(r[3]) : "r"(addr));
}

__device__ __forceinline__ void cp16(uint32_t saddr, const void* gptr){
    asm volatile("cp.async.cg.shared.global [%0], [%1], 16;" :: "r"(saddr), "l"(gptr));
}

// ===== split-bf16 GEMM: 128x256 tile, BK=32, 1024 threads ==================
// Pair-pipelined: 2 pair-sets x 2 tiles (4 stage buffers); ONE sync + ONE
// wait per 2 k-tiles. Stage (48KB): Ah[8KB] Al[8KB] B0[16KB] B1[16KB].
#define GSTG 49152u
#define GEMM_SMEM (4*49152)    // 196608 B

__device__ __forceinline__ void gemm_core(
    const uint32_t* __restrict__ Ah, const uint32_t* __restrict__ Al,
    const uint4* __restrict__ Bp0, const uint4* __restrict__ Bp1,
    const float* __restrict__ bias, float* __restrict__ out,
    int heads_mode, int S_rows, int L, int s_off,
    int row0, int colblk0, uint32_t* sm)
{
    const int tid = threadIdx.x, lane = tid & 31, wrp = tid >> 5;
    const int g = lane >> 2, t = lane & 3;
    const int wm = wrp >> 3;
    const int wnl = wrp & 7;
    const int j = wnl >> 2;
    const int wn4 = wnl & 3;

    float acc[2][4][4];
    #pragma unroll
    for (int i=0;i<2;i++)
        #pragma unroll
        for (int jj=0;jj<4;jj++)
            #pragma unroll
            for (int r=0;r<4;r++) acc[i][jj][r]=0.f;

    const uint32_t sbase = (uint32_t)__cvta_generic_to_shared(sm);
    uint32_t a_off[2][2];
    #pragma unroll
    for (int mt=0; mt<2; mt++){
        int r = wm*32 + mt*16 + ((lane>>3)&1)*8 + (lane&7);
        int swz = (r>>1)&3;
        #pragma unroll
        for (int s=0; s<2; s++){
            int u = s*2 + (lane>>4);
            a_off[mt][s] = (uint32_t)(r*64 + ((u ^ swz)<<4));
        }
    }
    uint32_t b_slot[2][4];
    #pragma unroll
    for (int s=0; s<2; s++)
        #pragma unroll
        for (int nt=0; nt<4; nt++){
            int ntg = wn4*4 + nt;
            int lp = ((g*4+t) ^ (g>>1)) ^ ((ntg&1)<<2);
            b_slot[s][nt] = (uint32_t)(j*1024 + (s*16+ntg)*32 + lp);
        }

    const uint32_t aunit = (uint32_t)(tid & 511);
    const uint32_t ar = aunit >> 2, au = aunit & 3;
    const uint32_t a_so = (tid < 512 ? 0u : 8192u) + ar*64 + ((au ^ ((ar>>1)&3))<<4);
    const uint32_t* Asrc = (tid < 512) ? Ah : Al;

// fill both tiles of pair p_ into pair-set set_ (stages 2*set_ .. 2*set_+1)
#define FILLPAIR(p_, set_) { \
    uint32_t sb0 = sbase + (uint32_t)(set_)*2u*GSTG; \
    _Pragma("unroll") \
    for (int e_=0;e_<2;e_++){ \
        uint32_t tk_ = (uint32_t)(p_)*2u + (uint32_t)e_; \
        uint32_t sbe = sb0 + (uint32_t)e_*GSTG; \
        cp16(sbe + a_so, Asrc + (size_t)(row0+ar)*768 + tk_*16u + au*4); \
        cp16(sbe + 16384u + (uint32_t)tid*16u, Bp0 + (size_t)tk_*1024 + tid); \
        cp16(sbe + 32768u + (uint32_t)tid*16u, Bp1 + (size_t)tk_*1024 + tid); \
    } \
    asm volatile("cp.async.commit_group;" ::: "memory"); }

    FILLPAIR(0, 0);

    const int nP = 24;
    for (int p=0; p<nP; p++){
        asm volatile("cp.async.wait_group 0;" ::: "memory");
        __syncthreads();
        if (p+1 < nP) { FILLPAIR(p+1, (p+1)&1); }
        #pragma unroll
        for (int e=0;e<2;e++){
            const int st = (p&1)*2 + e;
            const uint32_t bufb = sbase + (uint32_t)st*GSTG;
            const uint4* Bs = (const uint4*)(sm + st*12288 + 4096);
            #pragma unroll
            for (int s=0;s<2;s++){
                uint32_t ah[2][4], al[2][4];
                #pragma unroll
                for (int mt=0;mt<2;mt++){
                    ldsm4(ah[mt], bufb + a_off[mt][s]);
                    ldsm4(al[mt], bufb + 8192u + a_off[mt][s]);
                }
                #pragma unroll
                for (int nt=0;nt<4;nt++){
                    uint4 kw = Bs[b_slot[s][nt]];
                    #pragma unroll
                    for (int mt=0;mt<2;mt++){
                        mma16(acc[mt][nt], ah[mt], kw.x, kw.y);
                        mma16(acc[mt][nt], ah[mt], kw.z, kw.w);
                        mma16(acc[mt][nt], al[mt], kw.x, kw.y);
                    }
                }
            }
        }
    }
#undef FILLPAIR

    #pragma unroll
    for (int mt=0;mt<2;mt++){
        int m0r = row0 + wm*32 + mt*16 + g;
        #pragma unroll
        for (int nt=0;nt<4;nt++){
            int c = (colblk0 + j)*128 + wn4*32 + nt*8 + t*2;
            float b0v = bias[c], b1v = bias[c+1];
            float2 v0 = make_float2(acc[mt][nt][0]+b0v, acc[mt][nt][1]+b1v);
            float2 v1 = make_float2(acc[mt][nt][2]+b0v, acc[mt][nt][3]+b1v);
            if (!heads_mode){
                *(float2*)&out[(size_t)m0r*1536 + c]     = v0;
                *(float2*)&out[(size_t)(m0r+8)*1536 + c] = v1;
            } else {
                int hh = c >> 6, hd = c & 63;
                int bb = m0r / S_rows, ss = m0r - bb*S_rows;
                *(float2*)&out[((size_t)(bb*NUM_H+hh)*L + s_off + ss)*64 + hd] = v0;
                int m1r = m0r + 8;
                int bb1 = m1r / S_rows, ss1 = m1r - bb1*S_rows;
                *(float2*)&out[((size_t)(bb1*NUM_H+hh)*L + s_off + ss1)*64 + hd] = v1;
            }
        }
    }
}

// merged QKV: y<32 hidden rows (M=4096), y>=32 encoder rows (M=1024)
__global__ void __launch_bounds__(1024, 1) gemm_qkv(
    const uint32_t* __restrict__ Hh, const uint32_t* __restrict__ Hl,
    const uint32_t* __restrict__ Eh, const uint32_t* __restrict__ El,
    const uint4* __restrict__ WP,
    const float* __restrict__ bq, const float* __restrict__ bk, const float* __restrict__ bv,
    const float* __restrict__ abq, const float* __restrict__ abk, const float* __restrict__ abv,
    float* __restrict__ q, float* __restrict__ k, float* __restrict__ v)
{
    extern __shared__ uint32_t sm[];
    const int z = blockIdx.z;
    const bool enc = (blockIdx.y >= 32);
    const uint32_t* Ah = enc ? Eh : Hh;
    const uint32_t* Al = enc ? El : Hl;
    const float* bi = enc ? ((z==0)? abq : (z==1)? abk : abv)
                          : ((z==0)? bq  : (z==1)? bk  : bv);
    float* out = (z==0)? q : (z==1)? k : v;
    int L = (z==0)? LQ : LK;
    int soff = enc ? ((z==0)? 1024 : 2048) : 0;
    int S_rows = enc ? 256 : 1024;
    int row0 = (enc ? (blockIdx.y - 32) : blockIdx.y) * 128;
    const uint4* Bp0 = WP + (size_t)(((enc?3:0)+z)*12 + blockIdx.x*2)*48*1024;
    gemm_core(Ah, Al, Bp0, Bp0 + 48*1024, bi, out, 1, S_rows, L, soff,
              row0, blockIdx.x*2, sm);
}

// merged output projection: y<32 hidden (M=4096), y>=32 encoder (M=1024)
__global__ void __launch_bounds__(1024, 1) gemm_out(
    const uint32_t* __restrict__ A0h, const uint32_t* __restrict__ A0l,
    const uint32_t* __restrict__ A1h, const uint32_t* __restrict__ A1l,
    const uint4* __restrict__ WP, int widx0,
    const float* __restrict__ b0, const float* __restrict__ b1,
    float* __restrict__ o0, float* __restrict__ o1)
{
    extern __shared__ uint32_t sm[];
    const bool enc = (blockIdx.y >= 32);
    const uint32_t* Ah = enc ? A1h : A0h;
    const uint32_t* Al = enc ? A1l : A0l;
    const float* bi = enc ? b1 : b0;
    float* out = enc ? o1 : o0;
    int row0 = (enc ? (blockIdx.y - 32) : blockIdx.y) * 128;
    const uint4* Bp0 = WP + (size_t)((widx0 + (enc?1:0))*12 + blockIdx.x*2)*48*1024;
    gemm_core(Ah, Al, Bp0, Bp0 + 48*1024, bi, out,
              0, 0, 0, 0, row0, blockIdx.x*2, sm);
}

// ---------------- operand pre-conversion ----------------
__global__ void __launch_bounds__(256) conv_a(
    const float* __restrict__ x, uint32_t* __restrict__ hi, uint32_t* __restrict__ lo, int n4)
{
    int i = blockIdx.x*256 + threadIdx.x;
    if (i >= n4) return;
    float4 f = ((const float4*)x)[i];
    uint2 h, l;
    split_pair(f.x, f.y, h.x, l.x);
    split_pair(f.z, f.w, h.y, l.y);
    ((uint2*)hi)[i] = h; ((uint2*)lo)[i] = l;
}

__global__ void __launch_bounds__(256) conv_wp(
    const float* w0, const float* w1, const float* w2, const float* w3,
    const float* w4, const float* w5, const float* w6, const float* w7,
    uint4* __restrict__ wp)
{
    __shared__ float sw[32][129];
    const int cb = blockIdx.x, tk = blockIdx.y, z = blockIdx.z;
    const float* W = (z==0)?w0:(z==1)?w1:(z==2)?w2:(z==3)?w3:(z==4)?w4:(z==5)?w5:(z==6)?w6:w7;
    const int tid = threadIdx.x;
    #pragma unroll
    for (int i=0;i<4;i++){
        int e = tid + i*256;
        int r = e>>5, c4 = (e&31)*4;
        float4 f = *(const float4*)&W[(size_t)(tk*32+r)*1536 + cb*128 + c4];
        sw[r][c4]=f.x; sw[r][c4+1]=f.y; sw[r][c4+2]=f.z; sw[r][c4+3]=f.w;
    }
    __syncthreads();
    uint4* dst = wp + (size_t)((z*12+cb)*48 + tk)*1024;
    #pragma unroll
    for (int i=0;i<4;i++){
        int slot = tid + i*256;
        int idx32 = slot>>5, lp = slot&31;
        int bs = idx32>>4, ntg = idx32&15;
        int base = lp ^ ((ntg&1)<<2);
        int gg = base>>2, bt = (base&3) ^ (gg>>1);
        int n = ntg*8 + gg;
        int k0 = bs*16 + 2*bt;
        uint4 w4;
        split_pair(sw[k0][n],   sw[k0+1][n], w4.x, w4.z);
        split_pair(sw[k0+8][n], sw[k0+9][n], w4.y, w4.w);
        dst[slot] = w4;
    }
}

// ---------------- two-phase stats ----------------
__global__ void __launch_bounds__(256) stats_part(
    const float* __restrict__ q, const float* __restrict__ k,
    float* __restrict__ ps, float* __restrict__ pss)
{
    const int bh = blockIdx.x, part = blockIdx.y, z = blockIdx.z;
    const int tx = threadIdx.x & 63;
    const int ty = threadIdx.x >> 6;
    const float* p = (z ? k : q) + (size_t)bh * (z ? LK : LQ) * 64;
    float s = 0.f, ss = 0.f;
    for (int i = part*256 + ty; i < part*256 + 256; i += 4) {
        float v = p[(size_t)i*64 + tx];
        s += v; ss += v*v;
    }
    __shared__ float sh1[4][64], sh2[4][64];
    sh1[ty][tx] = s; sh2[ty][tx] = ss;
    __syncthreads();
    if (ty == 0) {
        int o = ((z*96+bh)*4+part)*64 + tx;
        ps [o] = sh1[0][tx]+sh1[1][tx]+sh1[2][tx]+sh1[3][tx];
        pss[o] = sh2[0][tx]+sh2[1][tx]+sh2[2][tx]+sh2[3][tx];
    }
}

__global__ void __launch_bounds__(64) stats_fin(
    const float* __restrict__ ps, const float* __restrict__ pss,
    float* __restrict__ mq, float* __restrict__ sq,
    float* __restrict__ mk, float* __restrict__ sk)
{
    const int bh = blockIdx.x, z = blockIdx.y, tx = threadIdx.x;
    float s = 0.f, ss = 0.f;
    #pragma unroll
    for (int p=0;p<4;p++){
        s  += ps [((z*96+bh)*4+p)*64 + tx];
        ss += pss[((z*96+bh)*4+p)*64 + tx];
    }
    float m = s * (1.0f/1024.0f);
    float var = (ss - 1024.0f*m*m) * (1.0f/1023.0f);
    (z ? mk : mq)[bh*64+tx] = m;
    (z ? sk : sq)[bh*64+tx] = sqrtf(var + 1e-5f);
}

// ---------------- merged convert K/V: tiles {0..15, 32..35}, z: 0=K 1=V -----
__global__ void __launch_bounds__(256) convert_kv(
    const float* __restrict__ k, const float* __restrict__ v,
    const float* __restrict__ mk, const float* __restrict__ sk,
    uint4* __restrict__ kf, uint4* __restrict__ vf)
{
    const int x = blockIdx.x, bh = blockIdx.y, z = blockIdx.z;
    const int kt = (x < 16) ? x : x + 16;
    const int b = bh / 24, h = bh - b*24;
    const bool style = (z == 0) && (b & 1) && (kt < 16);

    __shared__ float sK[64][65];
    __shared__ float pa[64], pc[64];
    const int tid = threadIdx.x;
    const float* src = (z ? v : k) + ((size_t)bh*LK + kt*64)*64;

    if (style && tid < 64){
        int sbh = (b-1)*24 + h;
        float a = sk[sbh*64+tid] / sk[bh*64+tid];
        pa[tid] = a;
        pc[tid] = mk[sbh*64+tid] - mk[bh*64+tid]*a;
    }
    __syncthreads();
    #pragma unroll
    for (int i=0;i<16;i++){
        int e = tid + i*256;
        float xv = src[e];
        if (style) xv = fmaf(xv, pa[e&63], pc[e&63]);
        sK[e>>6][e&63] = xv;
    }
    __syncthreads();
    if (z == 0){
        uint4* dst = kf + ((size_t)bh*36 + kt)*1024;
        #pragma unroll
        for (int i=0;i<4;i++){
            int slot = tid + i*256;
            int lane = slot & 31, nt = (slot>>5)&7, s = slot>>8;
            int g = lane>>2, t = lane&3;
            int kv = nt*8+g, d0 = 16*s+2*t;
            uint4 w4;
            split_pair(sK[kv][d0],   sK[kv][d0+1], w4.x, w4.z);
            split_pair(sK[kv][d0+8], sK[kv][d0+9], w4.y, w4.w);
            dst[slot] = w4;
        }
    } else {
        uint4* dst = vf + ((size_t)bh*36 + kt)*1024;
        #pragma unroll
        for (int i=0;i<4;i++){
            int slot = tid + i*256;
            int lane = slot & 31, jn = (slot>>5)&7, s2 = slot>>8;
            int g = lane>>2, t = lane&3;
            int d = jn*8+g, r0 = 16*s2+2*t;
            uint4 w4;
            split_pair(sK[r0][d],   sK[r0+1][d], w4.x, w4.z);
            split_pair(sK[r0+8][d], sK[r0+9][d], w4.y, w4.w);
            dst[slot] = w4;
        }
    }
}

// ================= flash attention: inline Q styling, max-free softmax ======
// Q styling applies ONLY to hidden q-rows (qt<8); encoder queries pass through.
#define AT_SMEM (2*2048*16)

__global__ void __launch_bounds__(256, 2) attn_bf3(
    const float* __restrict__ Q,
    const float* __restrict__ mq, const float* __restrict__ sq,
    const uint4* __restrict__ KF, const uint4* __restrict__ VF,
    uint32_t* __restrict__ AOH, uint32_t* __restrict__ AOL,
    uint32_t* __restrict__ EOH, uint32_t* __restrict__ EOL)
{
    extern __shared__ uint4 sm4[];
    __shared__ float pa[64], pc[64];
    const int tid = threadIdx.x, lane = tid & 31, w = tid >> 5;
    const int g = lane >> 2, t = lane & 3;
    const int qt = blockIdx.x, h = blockIdx.y, b = blockIdx.z;
    const bool odd = (b & 1);
    const int nkt = odd ? 36 : 20;
    const size_t bh = (size_t)b*NUM_H + h;
    const float* Qg = Q + (bh*LQ + (size_t)qt*128) * 64;
    const uint4* Kg = KF + bh*36*1024;
    const uint4* Vg = VF + bh*36*1024;
    const uint4* KgS = Kg - (size_t)24*36*1024;
    const uint4* VgS = Vg - (size_t)24*36*1024;
    const uint32_t smem_base = (uint32_t)__cvta_generic_to_shared(sm4);
    const float QSCALE = 0.125f * 1.44269504088896f;
    const bool styleq = odd && (qt < 8);   // hidden q-rows only

    if (tid < 64){
        if (styleq){
            int sbh = (int)bh - 24;
            float a = sq[sbh*64+tid] / sq[bh*64+tid];
            pa[tid] = a * QSCALE;
            pc[tid] = (mq[sbh*64+tid] - mq[bh*64+tid]*a) * QSCALE;
        } else {
            pa[tid] = QSCALE; pc[tid] = 0.f;
        }
    }

#define STAGE(jj_, buf_) { \
    int kt_; const uint4 *kb_, *vb_; \
    if (odd){ \
        if ((jj_) >= 16 && (jj_) < 32){ kt_ = (jj_) - 16; kb_ = KgS; vb_ = VgS; } \
        else { kt_ = (jj_); kb_ = Kg; vb_ = Vg; } \
    } else { \
        kt_ = ((jj_) < 16) ? (jj_) : (jj_) + 16; kb_ = Kg; vb_ = Vg; \
    } \
    uint32_t sb = smem_base + (buf_)*32768u; \
    const uint4* kp = kb_ + (size_t)kt_*1024 + tid; \
    const uint4* vp = vb_ + (size_t)kt_*1024 + tid; \
    _Pragma("unroll") \
    for (int i_=0;i_<4;i_++){ \
        cp16(sb + (uint32_t)(tid + i_*256)*16u,           kp + i_*256); \
        cp16(sb + 16384u + (uint32_t)(tid + i_*256)*16u,  vp + i_*256); \
    } \
    asm volatile("cp.async.commit_group;"); }

    STAGE(0, 0);
    __syncthreads();   // pa/pc visible

    uint32_t qh[4][4], ql[4][4];
    {
        const int r0 = w*16 + g;
        #pragma unroll
        for (int s=0;s<4;s++){
            int d0 = 16*s + 2*t;
            float2 x00 = *(const float2*)&Qg[(size_t)r0*64 + d0];
            float2 x10 = *(const float2*)&Qg[(size_t)(r0+8)*64 + d0];
            float2 x01 = *(const float2*)&Qg[(size_t)r0*64 + d0 + 8];
            float2 x11 = *(const float2*)&Qg[(size_t)(r0+8)*64 + d0 + 8];
            float a0 = pa[d0],   c0 = pc[d0];
            float a1 = pa[d0+1], c1 = pc[d0+1];
            float a8 = pa[d0+8], c8 = pc[d0+8];
            float a9 = pa[d0+9], c9 = pc[d0+9];
            split_pair(fmaf(x00.x,a0,c0), fmaf(x00.y,a1,c1), qh[s][0], ql[s][0]);
            split_pair(fmaf(x10.x,a0,c0), fmaf(x10.y,a1,c1), qh[s][1], ql[s][1]);
            split_pair(fmaf(x01.x,a8,c8), fmaf(x01.y,a9,c9), qh[s][2], ql[s][2]);
            split_pair(fmaf(x11.x,a8,c8), fmaf(x11.y,a9,c9), qh[s][3], ql[s][3]);
        }
    }

    float o_[8][4];
    #pragma unroll
    for (int jq=0;jq<8;jq++){ o_[jq][0]=0.f; o_[jq][1]=0.f; o_[jq][2]=0.f; o_[jq][3]=0.f; }
    float l0s=0.f, l1s=0.f;

    for (int jj=0; jj<nkt; jj++){
        asm volatile("cp.async.wait_group 0;");
        __syncthreads();
        if (jj+1 < nkt) { STAGE(jj+1, (jj+1)&1); }

        const uint4* Kt = sm4 + (jj&1)*2048;
        const uint4* Vt = Kt + 1024;
        const float padd = (!odd && jj < 16) ? 1.0f : 0.0f;

        float s_[8][4];
        #pragma unroll
        for (int jq=0;jq<8;jq++){ s_[jq][0]=0.f; s_[jq][1]=0.f; s_[jq][2]=0.f; s_[jq][3]=0.f; }
        #pragma unroll
        for (int s=0;s<4;s++)
            #pragma unroll
            for (int nt=0;nt<8;nt++){
                uint4 kw = Kt[(s*8+nt)*32 + lane];
                mma16(s_[nt], qh[s], kw.x, kw.y);
                mma16(s_[nt], qh[s], kw.z, kw.w);
                mma16(s_[nt], ql[s], kw.x, kw.y);
            }

        #pragma unroll
        for (int jq=0;jq<8;jq++){
            s_[jq][0]=exp2f(s_[jq][0]+padd); s_[jq][1]=exp2f(s_[jq][1]+padd);
            s_[jq][2]=exp2f(s_[jq][2]+padd); s_[jq][3]=exp2f(s_[jq][3]+padd);
            l0s += s_[jq][0]+s_[jq][1];
            l1s += s_[jq][2]+s_[jq][3];
        }

        uint32_t ph[4][4], pl[4][4];
        #pragma unroll
        for (int s2=0;s2<4;s2++){
            split_pair(s_[2*s2][0],   s_[2*s2][1],   ph[s2][0], pl[s2][0]);
            split_pair(s_[2*s2][2],   s_[2*s2][3],   ph[s2][1], pl[s2][1]);
            split_pair(s_[2*s2+1][0], s_[2*s2+1][1], ph[s2][2], pl[s2][2]);
            split_pair(s_[2*s2+1][2], s_[2*s2+1][3], ph[s2][3], pl[s2][3]);
        }

        #pragma unroll
        for (int s2=0;s2<4;s2++)
            #pragma unroll
            for (int jq=0;jq<8;jq++){
                uint4 vw = Vt[(s2*8+jq)*32 + lane];
                mma16(o_[jq], ph[s2], vw.x, vw.y);
                mma16(o_[jq], ph[s2], vw.z, vw.w);
                mma16(o_[jq], pl[s2], vw.x, vw.y);
            }
    }
#undef STAGE

    l0s += __shfl_xor_sync(0xffffffffu, l0s, 1);
    l0s += __shfl_xor_sync(0xffffffffu, l0s, 2);
    l1s += __shfl_xor_sync(0xffffffffu, l1s, 1);
    l1s += __shfl_xor_sync(0xffffffffu, l1s, 2);
    float inv0 = 1.0f / l0s, inv1 = 1.0f / l1s;
    int q0 = qt*128 + w*16 + g;

    uint32_t *OH, *OL;
    size_t rbase;
    if (q0 < 1024){ OH = AOH; OL = AOL; rbase = (size_t)(b*1024 + q0)*768; }
    else          { OH = EOH; OL = EOL; rbase = (size_t)(b*256 + q0 - 1024)*768; }
    #pragma unroll
    for (int jq=0;jq<8;jq++){
        int cw = h*32 + jq*4 + t;
        uint32_t hh, ll;
        split_pair(o_[jq][0]*inv0, o_[jq][1]*inv0, hh, ll);
        OH[rbase + cw] = hh; OL[rbase + cw] = ll;
        split_pair(o_[jq][2]*inv1, o_[jq][3]*inv1, hh, ll);
        OH[rbase + 8*768 + cw] = hh; OL[rbase + 8*768 + cw] = ll;
    }
}

// ---------------- launch ----------------
extern "C" void kernel_launch(void* const* d_in, const int* in_sizes, int n_in,
                              void* d_out, int out_size)
{
    (void)in_sizes; (void)n_in; (void)out_size;
    const float* hs  = (const float*)d_in[0];
    const float* ehs = (const float*)d_in[1];
    const float* wq  = (const float*)d_in[2];  const float* bq  = (const float*)d_in[3];
    const float* wk  = (const float*)d_in[4];  const float* bk  = (const float*)d_in[5];
    const float* wv  = (const float*)d_in[6];  const float* bv  = (const float*)d_in[7];
    const float* awq = (const float*)d_in[8];  const float* abq = (const float*)d_in[9];
    const float* awk = (const float*)d_in[10]; const float* abk = (const float*)d_in[11];
    const float* awv = (const float*)d_in[12]; const float* abv = (const float*)d_in[13];
    const float* wo  = (const float*)d_in[14]; const float* bo  = (const float*)d_in[15];
    const float* wao = (const float*)d_in[16]; const float* bao = (const float*)d_in[17];
    float* out = (float*)d_out;

    float *q, *k, *v, *mq, *sq, *mk, *sk, *ps, *pss;
    uint4 *kf, *vf, *wp;
    uint32_t *hsh, *hsl, *esh, *esl, *aoh, *aol, *eoh, *eol;
    cudaGetSymbolAddress((void**)&q,  g_q);
    cudaGetSymbolAddress((void**)&k,  g_k);
    cudaGetSymbolAddress((void**)&v,  g_v);
    cudaGetSymbolAddress((void**)&mq, g_mq);
    cudaGetSymbolAddress((void**)&sq, g_sq);
    cudaGetSymbolAddress((void**)&mk, g_mk);
    cudaGetSymbolAddress((void**)&sk, g_sk);
    cudaGetSymbolAddress((void**)&ps, g_ps);
    cudaGetSymbolAddress((void**)&pss, g_pss);
    cudaGetSymbolAddress((void**)&kf, g_kf);
    cudaGetSymbolAddress((void**)&vf, g_vf);
    cudaGetSymbolAddress((void**)&wp, g_wp);
    cudaGetSymbolAddress((void**)&hsh, g_hsh);
    cudaGetSymbolAddress((void**)&hsl, g_hsl);
    cudaGetSymbolAddress((void**)&esh, g_esh);
    cudaGetSymbolAddress((void**)&esl, g_esl);
    cudaGetSymbolAddress((void**)&aoh, g_aoh);
    cudaGetSymbolAddress((void**)&aol, g_aol);
    cudaGetSymbolAddress((void**)&eoh, g_eoh);
    cudaGetSymbolAddress((void**)&eol, g_eol);

    static int attr_set = 0;
    if (!attr_set) {
        cudaFuncSetAttribute(gemm_qkv, cudaFuncAttributeMaxDynamicSharedMemorySize, GEMM_SMEM);
        cudaFuncSetAttribute(gemm_out, cudaFuncAttributeMaxDynamicSharedMemorySize, GEMM_SMEM);
        cudaFuncSetAttribute(attn_bf3, cudaFuncAttributeMaxDynamicSharedMemorySize, AT_SMEM);
        attr_set = 1;
    }

    conv_a<<<6144, 256>>>(hs,  hsh, hsl, 4096*384);
    conv_a<<<1536, 256>>>(ehs, esh, esl, 1024*384);
    conv_wp<<<dim3(12, 48, 8), 256>>>(wq, wk, wv, awq, awk, awv, wo, wao, wp);

    gemm_qkv<<<dim3(6, 40, 3), 1024, GEMM_SMEM>>>(
        hsh, hsl, esh, esl, wp,
        bq, bk, bv, abq, abk, abv, q, k, v);

    stats_part<<<dim3(96, 4, 2), 256>>>(q, k, ps, pss);
    stats_fin<<<dim3(96, 2), 64>>>(ps, pss, mq, sq, mk, sk);

    convert_kv<<<dim3(20, 96, 2), 256>>>(k, v, mk, sk, kf, vf);

    attn_bf3<<<dim3(10, 24, 4), 256, AT_SMEM>>>(q, mq, sq, kf, vf, aoh, aol, eoh, eol);

    gemm_out<<<dim3(6, 40), 1024, GEMM_SMEM>>>(
        aoh, aol, eoh, eol, wp, 6, bo, bao,
        out, out + (size_t)4096*1536);
}